// round 1
// baseline (speedup 1.0000x reference)
#include <cuda_runtime.h>
#include <math.h>

#define NCG 8
#define SDIM 64
#define PH 66
#define PW 68
#define NPX 4096
#define NTH 256

struct Sm {
    float gxp[NCG][PH][PW];   // zero-padded input tile (padded row/col +1)
    float rowsum[NCG][SDIM];
    float colsum[NCG][SDIM];
    float sh[NCG][SDIM];      // sigmoid(row-gate)
    float sw[NCG][SDIM];      // sigmoid(col-gate)
    float wt[NPX];            // final per-pixel sigmoid weights
    float w1s[64];
    float w3s[576];
    float b1s[8], b3s[8], gnws[8], gnbs[8];
    float T[8], S2l[8], Sg[8], Sg2[8], mu[8], rsg[8];
    float x11[8], x21[8], Aarr[8], Kpart[8], beffp[8];
    float Weff[72];
    float Kc, beff;
};

__device__ __forceinline__ float sigf(float v) {
    return 1.0f / (1.0f + __expf(-v));
}

__global__ void __launch_bounds__(NTH, 1)
fused_kernel(const float* __restrict__ x,
             const float* __restrict__ w1, const float* __restrict__ b1,
             const float* __restrict__ w3, const float* __restrict__ b3,
             const float* __restrict__ gnw, const float* __restrict__ gnb,
             float* __restrict__ out)
{
    extern __shared__ char smraw[];
    Sm& s = *reinterpret_cast<Sm*>(smraw);
    const int tid = threadIdx.x;
    const long long g = blockIdx.x;
    const float* src = x + g * 32768;
    float* dst = out + g * 32768;

    // ---- zero the padded tile (float4, aligned) + load small params ----
    {
        float4 z4 = make_float4(0.f, 0.f, 0.f, 0.f);
        float4* gz = reinterpret_cast<float4*>(&s.gxp[0][0][0]);
        const int nz = NCG * PH * PW / 4;
        #pragma unroll 4
        for (int t = tid; t < nz; t += NTH) gz[t] = z4;
    }
    if (tid < 64) s.w1s[tid] = w1[tid];
    if (tid >= 64 && tid < 72) {
        int c = tid - 64;
        s.b1s[c] = b1[c]; s.b3s[c] = b3[c];
        s.gnws[c] = gnw[c]; s.gnbs[c] = gnb[c];
    }
    for (int t = tid; t < 576; t += NTH) s.w3s[t] = w3[t];
    __syncthreads();

    // ---- load tile: coalesced scalar LDG -> conflict-free STS ----
    #pragma unroll 8
    for (int k = 0; k < 128; k++) {
        int l = tid + NTH * k;
        float v = src[l];
        int c = l >> 12;
        int i = (l >> 6) & 63;
        int j = l & 63;
        s.gxp[c][i + 1][j + 1] = v;
    }
    __syncthreads();

    // ---- row sums (vector, borders are zero) & col sums ----
    for (int t = tid; t < 512; t += NTH) {
        int c = t >> 6, i = t & 63;
        const float4* rp = reinterpret_cast<const float4*>(&s.gxp[c][i + 1][0]);
        float rsum = 0.f;
        #pragma unroll
        for (int q = 0; q < PW / 4; q++) {
            float4 v = rp[q];
            rsum += (v.x + v.y) + (v.z + v.w);
        }
        s.rowsum[c][i] = rsum;
        float csum = 0.f;
        #pragma unroll 8
        for (int r = 0; r < 64; r++) csum += s.gxp[c][r + 1][i + 1];
        s.colsum[c][i] = csum;
    }
    __syncthreads();

    // ---- gate vectors sh/sw (w1 mix + sigmoid) and per-channel totals T ----
    for (int t = tid; t < 1024; t += NTH) {
        int kind = t >> 9;
        int o = (t >> 6) & 7;
        int i = t & 63;
        const float inv = 1.0f / 64.0f;
        float acc = s.b1s[o];
        if (kind == 0) {
            #pragma unroll
            for (int c = 0; c < 8; c++) acc += s.w1s[o * 8 + c] * (s.rowsum[c][i] * inv);
            s.sh[o][i] = sigf(acc);
        } else {
            #pragma unroll
            for (int c = 0; c < 8; c++) acc += s.w1s[o * 8 + c] * (s.colsum[c][i] * inv);
            s.sw[o][i] = sigf(acc);
        }
    }
    if (tid < 8) {
        float t0 = 0.f;
        #pragma unroll 8
        for (int i = 0; i < 64; i++) t0 += s.rowsum[tid][i];
        s.T[tid] = t0;
    }
    __syncthreads();

    // ---- conv-mean logits for x21 via shifted-window sums (closed form) ----
    if (tid < 8) {
        int c = tid;
        float acc = 0.f;
        #pragma unroll
        for (int ci = 0; ci < 8; ci++) {
            float T   = s.T[ci];
            float r0  = s.rowsum[ci][0],  r63 = s.rowsum[ci][63];
            float c0  = s.colsum[ci][0],  c63 = s.colsum[ci][63];
            float g00 = s.gxp[ci][1][1],  g0e = s.gxp[ci][1][64];
            float ge0 = s.gxp[ci][64][1], gee = s.gxp[ci][64][64];
            float Sv[9];
            Sv[0] = T - r63 - c63 + gee;  // dy=-1,dx=-1
            Sv[1] = T - r63;              // dy=-1,dx= 0
            Sv[2] = T - r63 - c0 + ge0;   // dy=-1,dx=+1
            Sv[3] = T - c63;              // dy= 0,dx=-1
            Sv[4] = T;
            Sv[5] = T - c0;               // dy= 0,dx=+1
            Sv[6] = T - r0 - c63 + g0e;   // dy=+1,dx=-1
            Sv[7] = T - r0;               // dy=+1,dx= 0
            Sv[8] = T - r0 - c0 + g00;    // dy=+1,dx=+1
            const float* wp = &s.w3s[c * 72 + ci * 9];
            #pragma unroll
            for (int t = 0; t < 9; t++) acc += wp[t] * Sv[t];
        }
        s.S2l[c] = acc * (1.0f / 4096.0f) + s.b3s[c];
    }

    // ---- gated statistics: one warp per channel ----
    {
        int c = tid >> 5;
        int lane = tid & 31;
        float sw0 = s.sw[c][lane], sw1 = s.sw[c][lane + 32];
        float sum = 0.f, sq = 0.f;
        #pragma unroll 4
        for (int i = 0; i < 64; i++) {
            float shi = s.sh[c][i];
            float v0 = s.gxp[c][i + 1][lane + 1]  * (shi * sw0);
            float v1 = s.gxp[c][i + 1][lane + 33] * (shi * sw1);
            sum += v0 + v1;
            sq  += v0 * v0 + v1 * v1;
        }
        #pragma unroll
        for (int off = 16; off; off >>= 1) {
            sum += __shfl_xor_sync(0xffffffffu, sum, off);
            sq  += __shfl_xor_sync(0xffffffffu, sq,  off);
        }
        if (lane == 0) { s.Sg[c] = sum; s.Sg2[c] = sq; }
    }
    __syncthreads();

    if (tid < 8) {
        float m = s.Sg[tid] * (1.0f / 4096.0f);
        float var = s.Sg2[tid] * (1.0f / 4096.0f) - m * m;
        s.mu[tid] = m;
        s.rsg[tid] = rsqrtf(var + 1e-5f);
    }
    __syncthreads();

    // ---- softmaxes (x1-mean == gn_b analytically) + fused coefficients ----
    if (tid < 8) {
        int c = tid;
        float mx1 = -1e30f, mx2 = -1e30f;
        #pragma unroll
        for (int k = 0; k < 8; k++) {
            mx1 = fmaxf(mx1, s.gnbs[k]);
            mx2 = fmaxf(mx2, s.S2l[k]);
        }
        float d1 = 0.f, d2 = 0.f;
        #pragma unroll
        for (int k = 0; k < 8; k++) {
            d1 += __expf(s.gnbs[k] - mx1);
            d2 += __expf(s.S2l[k] - mx2);
        }
        float x11 = __expf(s.gnbs[c] - mx1) / d1;
        float x21 = __expf(s.S2l[c] - mx2) / d2;
        s.x11[c] = x11;
        s.x21[c] = x21;
        float gr = s.gnws[c] * s.rsg[c];
        s.Aarr[c]  = x21 * gr;
        s.Kpart[c] = x21 * (s.gnbs[c] - gr * s.mu[c]);
        s.beffp[c] = x11 * s.b3s[c];
    }
    __syncthreads();

    // ---- collapse w3 over output channels with x11 -> Weff ----
    if (tid < 72) {
        int ci = tid / 9, tap = tid % 9;
        float acc = 0.f;
        #pragma unroll
        for (int o = 0; o < 8; o++) acc += s.x11[o] * s.w3s[o * 72 + ci * 9 + tap];
        s.Weff[tid] = acc;
    } else if (tid == 72) {
        float k = 0.f, b = 0.f;
        #pragma unroll
        for (int c = 0; c < 8; c++) { k += s.Kpart[c]; b += s.beffp[c]; }
        s.Kc = k; s.beff = b;
    }
    __syncthreads();

    // ---- F1: fused conv(Weff) + gated-norm term -> y -> sigmoid -> wt ----
    {
        float we[72];
        #pragma unroll
        for (int t = 0; t < 72; t++) we[t] = s.Weff[t];
        float areg[8];
        #pragma unroll
        for (int c = 0; c < 8; c++) areg[c] = s.Aarr[c];
        const float basec = s.Kc + s.beff;

        #pragma unroll
        for (int k = 0; k < 2; k++) {
            int pidx = tid + NTH * k;
            int i0 = (pidx >> 4) << 1;   // output rows i0, i0+1
            int j0 = (pidx & 15) << 2;   // output cols j0..j0+3
            float acc0[4], acc1[4];
            #pragma unroll
            for (int p = 0; p < 4; p++) { acc0[p] = basec; acc1[p] = basec; }

            #pragma unroll
            for (int ci = 0; ci < 8; ci++) {
                const float* bp = &s.gxp[ci][i0][j0];
                float4 ra0 = *(const float4*)(bp);
                float4 rb0 = *(const float4*)(bp + 4);
                float4 ra1 = *(const float4*)(bp + PW);
                float4 rb1 = *(const float4*)(bp + PW + 4);
                float4 ra2 = *(const float4*)(bp + 2 * PW);
                float4 rb2 = *(const float4*)(bp + 2 * PW + 4);
                float4 ra3 = *(const float4*)(bp + 3 * PW);
                float4 rb3 = *(const float4*)(bp + 3 * PW + 4);
                float w0[8]  = {ra0.x, ra0.y, ra0.z, ra0.w, rb0.x, rb0.y, rb0.z, rb0.w};
                float w1r[8] = {ra1.x, ra1.y, ra1.z, ra1.w, rb1.x, rb1.y, rb1.z, rb1.w};
                float w2r[8] = {ra2.x, ra2.y, ra2.z, ra2.w, rb2.x, rb2.y, rb2.z, rb2.w};
                float w3r[8] = {ra3.x, ra3.y, ra3.z, ra3.w, rb3.x, rb3.y, rb3.z, rb3.w};
                const float* wc = &we[ci * 9];
                #pragma unroll
                for (int p = 0; p < 4; p++) {
                    acc0[p] += wc[0]*w0[p]  + wc[1]*w0[p+1]  + wc[2]*w0[p+2]
                             + wc[3]*w1r[p] + wc[4]*w1r[p+1] + wc[5]*w1r[p+2]
                             + wc[6]*w2r[p] + wc[7]*w2r[p+1] + wc[8]*w2r[p+2];
                    acc1[p] += wc[0]*w1r[p] + wc[1]*w1r[p+1] + wc[2]*w1r[p+2]
                             + wc[3]*w2r[p] + wc[4]*w2r[p+1] + wc[5]*w2r[p+2]
                             + wc[6]*w3r[p] + wc[7]*w3r[p+1] + wc[8]*w3r[p+2];
                }
                float coef0 = areg[ci] * s.sh[ci][i0];
                float coef1 = areg[ci] * s.sh[ci][i0 + 1];
                float4 swv = *(const float4*)&s.sw[ci][j0];
                float swp[4] = {swv.x, swv.y, swv.z, swv.w};
                #pragma unroll
                for (int p = 0; p < 4; p++) {
                    acc0[p] += coef0 * swp[p] * w1r[p + 1];
                    acc1[p] += coef1 * swp[p] * w2r[p + 1];
                }
            }
            *(float4*)&s.wt[i0 * 64 + j0] =
                make_float4(sigf(acc0[0]), sigf(acc0[1]), sigf(acc0[2]), sigf(acc0[3]));
            *(float4*)&s.wt[(i0 + 1) * 64 + j0] =
                make_float4(sigf(acc1[0]), sigf(acc1[1]), sigf(acc1[2]), sigf(acc1[3]));
        }
    }
    __syncthreads();

    // ---- F2: out = gx * weights (coalesced) ----
    #pragma unroll 4
    for (int k = 0; k < 128; k++) {
        int l = tid + NTH * k;
        int c = l >> 12;
        int i = (l >> 6) & 63;
        int j = l & 63;
        dst[l] = s.gxp[c][i + 1][j + 1] * s.wt[l & 4095];
    }
}

extern "C" void kernel_launch(void* const* d_in, const int* in_sizes, int n_in,
                              void* d_out, int out_size) {
    (void)in_sizes; (void)n_in; (void)out_size;
    const float* x   = (const float*)d_in[0];
    const float* w1  = (const float*)d_in[1];
    const float* b1  = (const float*)d_in[2];
    const float* w3  = (const float*)d_in[3];
    const float* b3  = (const float*)d_in[4];
    const float* gnw = (const float*)d_in[5];
    const float* gnb = (const float*)d_in[6];
    float* out = (float*)d_out;

    size_t smem = sizeof(Sm);
    cudaFuncSetAttribute(fused_kernel, cudaFuncAttributeMaxDynamicSharedMemorySize, (int)smem);
    fused_kernel<<<1024, NTH, smem>>>(x, w1, b1, w3, b3, gnw, gnb, out);
}

// round 3
// speedup vs baseline: 1.3799x; 1.3799x over previous
#include <cuda_runtime.h>
#include <math.h>

#define NCG 8
#define SDIM 64
#define PH 66
#define PW 68
#define NPX 4096
#define NTH 512

struct Sm {
    float gxp[NCG][PH][PW];   // zero-bordered input tile (interior at [1..64][1..64])
    float rowsum[NCG][SDIM];
    float colsum[NCG][SDIM];
    float sh[NCG][SDIM];      // sigmoid(row-gate)
    float sw[NCG][SDIM];      // sigmoid(col-gate)
    float wt[NPX];            // final per-pixel sigmoid weights
    float w1s[64];
    float w3s[576];
    float b1s[8], b3s[8], gnws[8], gnbs[8];
    float T[8], S2l[8], mu[8], rsg[8];
    float Sgp[8][2], Sg2p[8][2];
    float x11[8], x21[8], Aarr[8], Kpart[8], beffp[8];
    float Weff[72];
    float Kc, beff;
};

__device__ __forceinline__ float sigf(float v) {
    return 1.0f / (1.0f + __expf(-v));
}

__global__ void __launch_bounds__(NTH, 1)
fused_kernel(const float* __restrict__ x,
             const float* __restrict__ w1, const float* __restrict__ b1,
             const float* __restrict__ w3, const float* __restrict__ b3,
             const float* __restrict__ gnw, const float* __restrict__ gnb,
             float* __restrict__ out)
{
    extern __shared__ char smraw[];
    Sm& s = *reinterpret_cast<Sm*>(smraw);
    const int tid = threadIdx.x;
    const long long g = blockIdx.x;
    const float* src = x + g * 32768;
    float* dst = out + g * 32768;

    // ---- phase A (independent writes): border zero + params + tile load ----
    // borders per channel: rows 0 & 65 full (68 each), rows 1..64 cols {0,65,66,67}
    for (int t = tid; t < 8 * 392; t += NTH) {
        int c = t / 392;
        int r = t % 392;
        if (r < 136) {
            int row = (r < 68) ? 0 : 65;
            int col = (r < 68) ? r : (r - 68);
            s.gxp[c][row][col] = 0.f;
        } else {
            int rr = r - 136;
            int row = (rr >> 2) + 1;
            int cs = rr & 3;
            int col = (cs == 0) ? 0 : (64 + cs);
            s.gxp[c][row][col] = 0.f;
        }
    }
    if (tid < 64) s.w1s[tid] = w1[tid];
    if (tid >= 64 && tid < 72) {
        int c = tid - 64;
        s.b1s[c] = b1[c]; s.b3s[c] = b3[c];
        s.gnws[c] = gnw[c]; s.gnbs[c] = gnb[c];
    }
    for (int t = tid; t < 576; t += NTH) s.w3s[t] = w3[t];

    // tile load: coalesced scalar LDG -> conflict-free STS (interior only)
    #pragma unroll 8
    for (int k = 0; k < 64; k++) {
        int l = tid + NTH * k;
        float v = src[l];
        int c = l >> 12;
        int i = (l >> 6) & 63;
        int j = l & 63;
        s.gxp[c][i + 1][j + 1] = v;
    }
    __syncthreads();

    // ---- row sums (vector float4, borders zero) & col sums ----
    if (tid < 512) {
        int c = tid >> 6, i = tid & 63;
        const float4* rp = reinterpret_cast<const float4*>(&s.gxp[c][i + 1][0]);
        float rsum = 0.f;
        #pragma unroll
        for (int q = 0; q < PW / 4; q++) {
            float4 v = rp[q];
            rsum += (v.x + v.y) + (v.z + v.w);
        }
        s.rowsum[c][i] = rsum;
        float csum = 0.f;
        #pragma unroll 8
        for (int r = 0; r < 64; r++) csum += s.gxp[c][r + 1][i + 1];
        s.colsum[c][i] = csum;
    }
    __syncthreads();

    // ---- gate vectors sh/sw (w1 mix + sigmoid) and per-channel totals T ----
    #pragma unroll
    for (int k = 0; k < 2; k++) {
        int t = tid + NTH * k;
        int kind = t >> 9;
        int o = (t >> 6) & 7;
        int i = t & 63;
        const float inv = 1.0f / 64.0f;
        float acc = s.b1s[o];
        if (kind == 0) {
            #pragma unroll
            for (int c = 0; c < 8; c++) acc += s.w1s[o * 8 + c] * (s.rowsum[c][i] * inv);
            s.sh[o][i] = sigf(acc);
        } else {
            #pragma unroll
            for (int c = 0; c < 8; c++) acc += s.w1s[o * 8 + c] * (s.colsum[c][i] * inv);
            s.sw[o][i] = sigf(acc);
        }
    }
    if (tid < 8) {
        float t0 = 0.f;
        #pragma unroll 8
        for (int i = 0; i < 64; i++) t0 += s.rowsum[tid][i];
        s.T[tid] = t0;
    }
    __syncthreads();

    // ---- conv-mean logits for x21 via shifted-window sums (closed form) ----
    if (tid < 8) {
        int c = tid;
        float acc = 0.f;
        #pragma unroll
        for (int ci = 0; ci < 8; ci++) {
            float T   = s.T[ci];
            float r0  = s.rowsum[ci][0],  r63 = s.rowsum[ci][63];
            float c0  = s.colsum[ci][0],  c63 = s.colsum[ci][63];
            float g00 = s.gxp[ci][1][1],  g0e = s.gxp[ci][1][64];
            float ge0 = s.gxp[ci][64][1], gee = s.gxp[ci][64][64];
            float Sv[9];
            Sv[0] = T - r63 - c63 + gee;
            Sv[1] = T - r63;
            Sv[2] = T - r63 - c0 + ge0;
            Sv[3] = T - c63;
            Sv[4] = T;
            Sv[5] = T - c0;
            Sv[6] = T - r0 - c63 + g0e;
            Sv[7] = T - r0;
            Sv[8] = T - r0 - c0 + g00;
            const float* wp = &s.w3s[c * 72 + ci * 9];
            #pragma unroll
            for (int t = 0; t < 9; t++) acc += wp[t] * Sv[t];
        }
        s.S2l[c] = acc * (1.0f / 4096.0f) + s.b3s[c];
    }

    // ---- gated statistics: 2 warps per channel (rows split) ----
    {
        int w = tid >> 5;
        int c = w >> 1;
        int half = w & 1;
        int lane = tid & 31;
        float sw0 = s.sw[c][lane], sw1 = s.sw[c][lane + 32];
        float sum = 0.f, sq = 0.f;
        int ibase = half * 32;
        #pragma unroll 4
        for (int r = 0; r < 32; r++) {
            int i = ibase + r;
            float shi = s.sh[c][i];
            float v0 = s.gxp[c][i + 1][lane + 1]  * (shi * sw0);
            float v1 = s.gxp[c][i + 1][lane + 33] * (shi * sw1);
            sum += v0 + v1;
            sq  += v0 * v0 + v1 * v1;
        }
        #pragma unroll
        for (int off = 16; off; off >>= 1) {
            sum += __shfl_xor_sync(0xffffffffu, sum, off);
            sq  += __shfl_xor_sync(0xffffffffu, sq,  off);
        }
        if (lane == 0) { s.Sgp[c][half] = sum; s.Sg2p[c][half] = sq; }
    }
    __syncthreads();

    if (tid < 8) {
        float m  = (s.Sgp[tid][0]  + s.Sgp[tid][1])  * (1.0f / 4096.0f);
        float q  = (s.Sg2p[tid][0] + s.Sg2p[tid][1]) * (1.0f / 4096.0f);
        float var = q - m * m;
        s.mu[tid] = m;
        s.rsg[tid] = rsqrtf(var + 1e-5f);
    }
    __syncthreads();

    // ---- softmaxes (x1-mean == gn_b analytically) + fused coefficients ----
    if (tid < 8) {
        int c = tid;
        float mx1 = -1e30f, mx2 = -1e30f;
        #pragma unroll
        for (int k = 0; k < 8; k++) {
            mx1 = fmaxf(mx1, s.gnbs[k]);
            mx2 = fmaxf(mx2, s.S2l[k]);
        }
        float d1 = 0.f, d2 = 0.f;
        #pragma unroll
        for (int k = 0; k < 8; k++) {
            d1 += __expf(s.gnbs[k] - mx1);
            d2 += __expf(s.S2l[k] - mx2);
        }
        float x11 = __expf(s.gnbs[c] - mx1) / d1;
        float x21 = __expf(s.S2l[c] - mx2) / d2;
        s.x11[c] = x11;
        s.x21[c] = x21;
        float gr = s.gnws[c] * s.rsg[c];
        s.Aarr[c]  = x21 * gr;
        s.Kpart[c] = x21 * (s.gnbs[c] - gr * s.mu[c]);
        s.beffp[c] = x11 * s.b3s[c];
    }
    __syncthreads();

    // ---- collapse w3 over output channels with x11 -> Weff ----
    if (tid < 72) {
        int ci = tid / 9, tap = tid % 9;
        float acc = 0.f;
        #pragma unroll
        for (int o = 0; o < 8; o++) acc += s.x11[o] * s.w3s[o * 72 + ci * 9 + tap];
        s.Weff[tid] = acc;
    } else if (tid == 72) {
        float k = 0.f, b = 0.f;
        #pragma unroll
        for (int c = 0; c < 8; c++) { k += s.Kpart[c]; b += s.beffp[c]; }
        s.Kc = k; s.beff = b;
    }
    __syncthreads();

    // ---- F1: fused conv(Weff) + gated-norm term -> y -> sigmoid -> wt ----
    {
        int pidx = tid;                  // 512 units, one per thread
        int i0 = (pidx >> 4) << 1;       // output rows i0, i0+1
        int j0 = (pidx & 15) << 2;       // output cols j0..j0+3
        const float basec = s.Kc + s.beff;
        float acc0[4], acc1[4];
        #pragma unroll
        for (int p = 0; p < 4; p++) { acc0[p] = basec; acc1[p] = basec; }

        #pragma unroll
        for (int ci = 0; ci < 8; ci++) {
            const float* bp = &s.gxp[ci][i0][j0];
            float4 ra0 = *(const float4*)(bp);
            float4 rb0 = *(const float4*)(bp + 4);
            float4 ra1 = *(const float4*)(bp + PW);
            float4 rb1 = *(const float4*)(bp + PW + 4);
            float4 ra2 = *(const float4*)(bp + 2 * PW);
            float4 rb2 = *(const float4*)(bp + 2 * PW + 4);
            float4 ra3 = *(const float4*)(bp + 3 * PW);
            float4 rb3 = *(const float4*)(bp + 3 * PW + 4);
            float w0[8]  = {ra0.x, ra0.y, ra0.z, ra0.w, rb0.x, rb0.y, rb0.z, rb0.w};
            float w1r[8] = {ra1.x, ra1.y, ra1.z, ra1.w, rb1.x, rb1.y, rb1.z, rb1.w};
            float w2r[8] = {ra2.x, ra2.y, ra2.z, ra2.w, rb2.x, rb2.y, rb2.z, rb2.w};
            float w3r[8] = {ra3.x, ra3.y, ra3.z, ra3.w, rb3.x, rb3.y, rb3.z, rb3.w};
            const float* wc = &s.Weff[ci * 9];   // warp-uniform broadcast LDS
            float c0w = wc[0], c1w = wc[1], c2w = wc[2];
            float c3w = wc[3], c4w = wc[4], c5w = wc[5];
            float c6w = wc[6], c7w = wc[7], c8w = wc[8];
            #pragma unroll
            for (int p = 0; p < 4; p++) {
                acc0[p] += c0w*w0[p]  + c1w*w0[p+1]  + c2w*w0[p+2]
                         + c3w*w1r[p] + c4w*w1r[p+1] + c5w*w1r[p+2]
                         + c6w*w2r[p] + c7w*w2r[p+1] + c8w*w2r[p+2];
                acc1[p] += c0w*w1r[p] + c1w*w1r[p+1] + c2w*w1r[p+2]
                         + c3w*w2r[p] + c4w*w2r[p+1] + c5w*w2r[p+2]
                         + c6w*w3r[p] + c7w*w3r[p+1] + c8w*w3r[p+2];
            }
            float aci = s.Aarr[ci];
            float coef0 = aci * s.sh[ci][i0];
            float coef1 = aci * s.sh[ci][i0 + 1];
            float4 swv = *(const float4*)&s.sw[ci][j0];
            float swp[4] = {swv.x, swv.y, swv.z, swv.w};
            #pragma unroll
            for (int p = 0; p < 4; p++) {
                acc0[p] += coef0 * swp[p] * w1r[p + 1];
                acc1[p] += coef1 * swp[p] * w2r[p + 1];
            }
        }
        *(float4*)&s.wt[i0 * 64 + j0] =
            make_float4(sigf(acc0[0]), sigf(acc0[1]), sigf(acc0[2]), sigf(acc0[3]));
        *(float4*)&s.wt[(i0 + 1) * 64 + j0] =
            make_float4(sigf(acc1[0]), sigf(acc1[1]), sigf(acc1[2]), sigf(acc1[3]));
    }
    __syncthreads();

    // ---- F2: out = gx * weights (coalesced, conflict-free scalar LDS) ----
    #pragma unroll 8
    for (int k = 0; k < 64; k++) {
        int l = tid + NTH * k;
        int c = l >> 12;
        int i = (l >> 6) & 63;
        int j = l & 63;
        dst[l] = s.gxp[c][i + 1][j + 1] * s.wt[l & 4095];
    }
}

extern "C" void kernel_launch(void* const* d_in, const int* in_sizes, int n_in,
                              void* d_out, int out_size) {
    (void)in_sizes; (void)n_in; (void)out_size;
    const float* x   = (const float*)d_in[0];
    const float* w1  = (const float*)d_in[1];
    const float* b1  = (const float*)d_in[2];
    const float* w3  = (const float*)d_in[3];
    const float* b3  = (const float*)d_in[4];
    const float* gnw = (const float*)d_in[5];
    const float* gnb = (const float*)d_in[6];
    float* out = (float*)d_out;

    size_t smem = sizeof(Sm);
    cudaFuncSetAttribute(fused_kernel, cudaFuncAttributeMaxDynamicSharedMemorySize, (int)smem);
    fused_kernel<<<1024, NTH, smem>>>(x, w1, b1, w3, b3, gnw, gnb, out);
}

// round 4
// speedup vs baseline: 1.4896x; 1.0795x over previous
#include <cuda_runtime.h>
#include <cstdint>
#include <math.h>

#define NCG 8
#define RR 32
#define PHh 34
#define PW 68
#define NTH 256

struct SmC {
    float tile[NCG][PHh][PW];   // padded local tile: rows 0/33 = halo or zero
    float excol[2][NCG][64];    // partial colsums per rank
    float exedge[2][NCG];       // rowsum of global row 0 / 63
    float excor[2][NCG][2];     // corners (g00,g0e) / (ge0,gee)
    float exsg[2][NCG];         // gated sum partials
    float exsg2[2][NCG];        // gated sumsq partials
    float rowsum[NCG][RR];
    float colm[NCG][64];        // merged colsums
    float sh[NCG][RR];          // row gates (own rows)
    float sw[NCG][64];          // col gates (all cols)
    float wt[RR * 64];          // per-pixel weights (own rows)
    float w1s[64];
    float w3s[576];
    float b1s[8], b3s[8], gnws[8], gnbs[8];
    float T[8], S2l[8];
    float Aarr[8], Kpart[8], x11s[8];
    float Weff[72];
    float Kc;
};

__device__ __forceinline__ float sigf(float v) {
    return 1.0f / (1.0f + __expf(-v));
}

__device__ __forceinline__ uint32_t s2u(const void* p) {
    uint32_t a;
    asm("{ .reg .u64 t; cvta.to.shared.u64 t, %1; cvt.u32.u64 %0, t; }" : "=r"(a) : "l"(p));
    return a;
}

__device__ __forceinline__ void st_peer(const void* laddr, uint32_t prank, float v) {
    uint32_t la = s2u(laddr);
    uint32_t ra;
    asm volatile("mapa.shared::cluster.u32 %0, %1, %2;" : "=r"(ra) : "r"(la), "r"(prank));
    asm volatile("st.shared::cluster.f32 [%0], %1;" :: "r"(ra), "f"(v) : "memory");
}

#define CLUSTER_SYNC() do { \
    asm volatile("barrier.cluster.arrive.aligned;" ::: "memory"); \
    asm volatile("barrier.cluster.wait.aligned;" ::: "memory"); \
} while (0)

__global__ void __launch_bounds__(NTH, 2) __cluster_dims__(2, 1, 1)
fused_kernel(const float* __restrict__ x,
             const float* __restrict__ w1, const float* __restrict__ b1,
             const float* __restrict__ w3, const float* __restrict__ b3,
             const float* __restrict__ gnw, const float* __restrict__ gnb,
             float* __restrict__ out)
{
    extern __shared__ char smraw[];
    SmC& s = *reinterpret_cast<SmC*>(smraw);
    const int tid = threadIdx.x;
    uint32_t rank;
    asm("mov.u32 %0, %%cluster_ctarank;" : "=r"(rank));
    const uint32_t prank = 1u - rank;
    const long long g = blockIdx.x >> 1;
    const int rbase = (int)rank * RR;
    const float* src = x + g * 32768;
    float* dst = out + g * 32768;
    const float4* src4 = reinterpret_cast<const float4*>(src);

    // ---- phase A: border zeros + params + tile load (+ halo row) ----
    for (int t = tid; t < 8 * 204; t += NTH) {
        int c = t / 204;
        int r = t % 204;
        if (r < 68) {
            int row = (rank == 0) ? 0 : 33;   // the outside halo row is zero
            s.tile[c][row][r] = 0.f;
        } else {
            int rr2 = r - 68;                 // 0..135
            int row = rr2 >> 2;               // 0..33
            int cs = rr2 & 3;
            int col = (cs == 0) ? 0 : (64 + cs);
            s.tile[c][row][col] = 0.f;
        }
    }
    if (tid < 64) s.w1s[tid] = w1[tid];
    if (tid >= 64 && tid < 72) {
        int c = tid - 64;
        s.b1s[c] = b1[c]; s.b3s[c] = b3[c];
        s.gnws[c] = gnw[c]; s.gnbs[c] = gnb[c];
    }
    for (int t = tid; t < 576; t += NTH) s.w3s[t] = w3[t];

    #pragma unroll 4
    for (int k = 0; k < 16; k++) {
        int l4 = tid + NTH * k;
        int c = l4 >> 9;
        int i = (l4 >> 4) & 31;
        int j4 = (l4 & 15) << 2;
        float4 v = src4[c * 1024 + (rbase + i) * 16 + (j4 >> 2)];
        float* p = &s.tile[c][i + 1][j4 + 1];
        p[0] = v.x; p[1] = v.y; p[2] = v.z; p[3] = v.w;
    }
    // inner halo row from gmem (always exists)
    if (tid < 128) {
        int c = tid >> 4;
        int j4 = (tid & 15) << 2;
        int grow = (rank == 0) ? 32 : 31;
        int prow = (rank == 0) ? 33 : 0;
        float4 v = src4[c * 1024 + grow * 16 + (j4 >> 2)];
        float* p = &s.tile[c][prow][j4 + 1];
        p[0] = v.x; p[1] = v.y; p[2] = v.z; p[3] = v.w;
    }
    __syncthreads();

    // ---- phase B: rowsums (local), colsum partials, edges, corners; exchange ----
    {
        int c = tid >> 5, i = tid & 31;
        const float4* rp = reinterpret_cast<const float4*>(&s.tile[c][i + 1][0]);
        float rsum = 0.f;
        #pragma unroll
        for (int q = 0; q < PW / 4; q++) {
            float4 v = rp[q];
            rsum += (v.x + v.y) + (v.z + v.w);
        }
        s.rowsum[c][i] = rsum;
        int edgei = (rank == 0) ? 0 : 31;
        if (i == edgei) {
            s.exedge[rank][c] = rsum;
            st_peer(&s.exedge[rank][c], prank, rsum);
        }
    }
    #pragma unroll
    for (int k = 0; k < 2; k++) {
        int t = tid + NTH * k;
        int c = t >> 6, j = t & 63;
        float csum = 0.f;
        #pragma unroll 8
        for (int r = 0; r < 32; r++) csum += s.tile[c][r + 1][j + 1];
        s.excol[rank][c][j] = csum;
        st_peer(&s.excol[rank][c][j], prank, csum);
    }
    if (tid < 8) {
        int c = tid;
        float a, b;
        if (rank == 0) { a = s.tile[c][1][1];  b = s.tile[c][1][64]; }
        else           { a = s.tile[c][32][1]; b = s.tile[c][32][64]; }
        s.excor[rank][c][0] = a;
        s.excor[rank][c][1] = b;
        st_peer(&s.excor[rank][c][0], prank, a);
        st_peer(&s.excor[rank][c][1], prank, b);
    }
    CLUSTER_SYNC();

    // ---- phase C: sh (local rows), merge colsums ----
    {
        int o = tid >> 5, i = tid & 31;
        const float inv = 1.0f / 64.0f;
        float acc = s.b1s[o];
        #pragma unroll
        for (int c = 0; c < 8; c++) acc += s.w1s[o * 8 + c] * (s.rowsum[c][i] * inv);
        s.sh[o][i] = sigf(acc);
    }
    #pragma unroll
    for (int k = 0; k < 2; k++) {
        int t = tid + NTH * k;
        int c = t >> 6, j = t & 63;
        s.colm[c][j] = s.excol[0][c][j] + s.excol[1][c][j];
    }
    __syncthreads();

    // ---- phase D: sw (all cols) + T ----
    #pragma unroll
    for (int k = 0; k < 2; k++) {
        int t = tid + NTH * k;
        int o = t >> 6, j = t & 63;
        const float inv = 1.0f / 64.0f;
        float acc = s.b1s[o];
        #pragma unroll
        for (int c = 0; c < 8; c++) acc += s.w1s[o * 8 + c] * (s.colm[c][j] * inv);
        s.sw[o][j] = sigf(acc);
    }
    if (tid < 8) {
        float t0 = 0.f;
        #pragma unroll 8
        for (int j = 0; j < 64; j++) t0 += s.colm[tid][j];
        s.T[tid] = t0;
    }
    __syncthreads();

    // ---- phase E: conv-mean logits S2l (closed form) + gated stats partials ----
    if (tid < 8) {
        int c = tid;
        float acc = 0.f;
        #pragma unroll
        for (int ci = 0; ci < 8; ci++) {
            float T   = s.T[ci];
            float r0  = s.exedge[0][ci], r63 = s.exedge[1][ci];
            float c0  = s.colm[ci][0],   c63 = s.colm[ci][63];
            float g00 = s.excor[0][ci][0], g0e = s.excor[0][ci][1];
            float ge0 = s.excor[1][ci][0], gee = s.excor[1][ci][1];
            float Sv[9];
            Sv[0] = T - r63 - c63 + gee;
            Sv[1] = T - r63;
            Sv[2] = T - r63 - c0 + ge0;
            Sv[3] = T - c63;
            Sv[4] = T;
            Sv[5] = T - c0;
            Sv[6] = T - r0 - c63 + g0e;
            Sv[7] = T - r0;
            Sv[8] = T - r0 - c0 + g00;
            const float* wp = &s.w3s[c * 72 + ci * 9];
            #pragma unroll
            for (int t = 0; t < 9; t++) acc += wp[t] * Sv[t];
        }
        s.S2l[c] = acc * (1.0f / 4096.0f) + s.b3s[c];
    }
    {
        int c = tid >> 5;
        int lane = tid & 31;
        float sw0 = s.sw[c][lane], sw1 = s.sw[c][lane + 32];
        float sum = 0.f, sq = 0.f;
        #pragma unroll 4
        for (int i = 0; i < 32; i++) {
            float shi = s.sh[c][i];
            float v0 = s.tile[c][i + 1][lane + 1]  * (shi * sw0);
            float v1 = s.tile[c][i + 1][lane + 33] * (shi * sw1);
            sum += v0 + v1;
            sq  += v0 * v0 + v1 * v1;
        }
        #pragma unroll
        for (int off = 16; off; off >>= 1) {
            sum += __shfl_xor_sync(0xffffffffu, sum, off);
            sq  += __shfl_xor_sync(0xffffffffu, sq,  off);
        }
        if (lane == 0) {
            s.exsg[rank][c] = sum;  s.exsg2[rank][c] = sq;
            st_peer(&s.exsg[rank][c],  prank, sum);
            st_peer(&s.exsg2[rank][c], prank, sq);
        }
    }
    CLUSTER_SYNC();

    // ---- phase F: norm stats + softmaxes + fused coefficients ----
    if (tid < 8) {
        int c = tid;
        float m = (s.exsg[0][c]  + s.exsg[1][c])  * (1.0f / 4096.0f);
        float q = (s.exsg2[0][c] + s.exsg2[1][c]) * (1.0f / 4096.0f);
        float rsg = rsqrtf(q - m * m + 1e-5f);
        float mx1 = -1e30f, mx2 = -1e30f;
        #pragma unroll
        for (int k = 0; k < 8; k++) {
            mx1 = fmaxf(mx1, s.gnbs[k]);
            mx2 = fmaxf(mx2, s.S2l[k]);
        }
        float d1 = 0.f, d2 = 0.f;
        #pragma unroll
        for (int k = 0; k < 8; k++) {
            d1 += __expf(s.gnbs[k] - mx1);
            d2 += __expf(s.S2l[k] - mx2);
        }
        float x11 = __expf(s.gnbs[c] - mx1) / d1;
        float x21 = __expf(s.S2l[c] - mx2) / d2;
        s.x11s[c] = x11;
        float gr = s.gnws[c] * rsg;
        s.Aarr[c]  = x21 * gr;
        s.Kpart[c] = x21 * (s.gnbs[c] - gr * m) + x11 * s.b3s[c];
    }
    __syncthreads();
    if (tid < 72) {
        int ci = tid / 9, tap = tid % 9;
        float acc = 0.f;
        #pragma unroll
        for (int o = 0; o < 8; o++) acc += s.x11s[o] * s.w3s[o * 72 + ci * 9 + tap];
        s.Weff[tid] = acc;
    } else if (tid == 72) {
        float k = 0.f;
        #pragma unroll
        for (int c = 0; c < 8; c++) k += s.Kpart[c];
        s.Kc = k;
    }
    __syncthreads();

    // ---- F1: fused conv(Weff) + gated-norm term -> sigmoid -> wt (own rows) ----
    {
        int i0 = (tid >> 4) << 1;      // local output rows i0, i0+1 (0..30)
        int j0 = (tid & 15) << 2;      // output cols j0..j0+3
        const float basec = s.Kc;
        float acc0[4], acc1[4];
        #pragma unroll
        for (int p = 0; p < 4; p++) { acc0[p] = basec; acc1[p] = basec; }

        #pragma unroll
        for (int ci = 0; ci < 8; ci++) {
            const float* bp = &s.tile[ci][i0][j0];
            float4 ra0 = *(const float4*)(bp);
            float4 rb0 = *(const float4*)(bp + 4);
            float4 ra1 = *(const float4*)(bp + PW);
            float4 rb1 = *(const float4*)(bp + PW + 4);
            float4 ra2 = *(const float4*)(bp + 2 * PW);
            float4 rb2 = *(const float4*)(bp + 2 * PW + 4);
            float4 ra3 = *(const float4*)(bp + 3 * PW);
            float4 rb3 = *(const float4*)(bp + 3 * PW + 4);
            float w0[8]  = {ra0.x, ra0.y, ra0.z, ra0.w, rb0.x, rb0.y, rb0.z, rb0.w};
            float w1r[8] = {ra1.x, ra1.y, ra1.z, ra1.w, rb1.x, rb1.y, rb1.z, rb1.w};
            float w2r[8] = {ra2.x, ra2.y, ra2.z, ra2.w, rb2.x, rb2.y, rb2.z, rb2.w};
            float w3r[8] = {ra3.x, ra3.y, ra3.z, ra3.w, rb3.x, rb3.y, rb3.z, rb3.w};
            const float* wc = &s.Weff[ci * 9];
            float c0w = wc[0], c1w = wc[1], c2w = wc[2];
            float c3w = wc[3], c4w = wc[4], c5w = wc[5];
            float c6w = wc[6], c7w = wc[7], c8w = wc[8];
            #pragma unroll
            for (int p = 0; p < 4; p++) {
                acc0[p] += c0w*w0[p]  + c1w*w0[p+1]  + c2w*w0[p+2]
                         + c3w*w1r[p] + c4w*w1r[p+1] + c5w*w1r[p+2]
                         + c6w*w2r[p] + c7w*w2r[p+1] + c8w*w2r[p+2];
                acc1[p] += c0w*w1r[p] + c1w*w1r[p+1] + c2w*w1r[p+2]
                         + c3w*w2r[p] + c4w*w2r[p+1] + c5w*w2r[p+2]
                         + c6w*w3r[p] + c7w*w3r[p+1] + c8w*w3r[p+2];
            }
            float aci = s.Aarr[ci];
            float coef0 = aci * s.sh[ci][i0];
            float coef1 = aci * s.sh[ci][i0 + 1];
            float4 swv = *(const float4*)&s.sw[ci][j0];
            float swp[4] = {swv.x, swv.y, swv.z, swv.w};
            #pragma unroll
            for (int p = 0; p < 4; p++) {
                acc0[p] += coef0 * swp[p] * w1r[p + 1];
                acc1[p] += coef1 * swp[p] * w2r[p + 1];
            }
        }
        *(float4*)&s.wt[i0 * 64 + j0] =
            make_float4(sigf(acc0[0]), sigf(acc0[1]), sigf(acc0[2]), sigf(acc0[3]));
        *(float4*)&s.wt[(i0 + 1) * 64 + j0] =
            make_float4(sigf(acc1[0]), sigf(acc1[1]), sigf(acc1[2]), sigf(acc1[3]));
    }
    __syncthreads();

    // ---- F2: out = gx * weights (float4 stores, own rows) ----
    #pragma unroll 4
    for (int k = 0; k < 16; k++) {
        int l4 = tid + NTH * k;
        int c = l4 >> 9;
        int i = (l4 >> 4) & 31;
        int j4 = (l4 & 15) << 2;
        float4 wv = *(const float4*)&s.wt[i * 64 + j4];
        const float* p = &s.tile[c][i + 1][j4 + 1];
        float4 o4 = make_float4(p[0] * wv.x, p[1] * wv.y, p[2] * wv.z, p[3] * wv.w);
        *reinterpret_cast<float4*>(&dst[c * 4096 + (rbase + i) * 64 + j4]) = o4;
    }
}

extern "C" void kernel_launch(void* const* d_in, const int* in_sizes, int n_in,
                              void* d_out, int out_size) {
    (void)in_sizes; (void)n_in; (void)out_size;
    const float* x   = (const float*)d_in[0];
    const float* w1  = (const float*)d_in[1];
    const float* b1  = (const float*)d_in[2];
    const float* w3  = (const float*)d_in[3];
    const float* b3  = (const float*)d_in[4];
    const float* gnw = (const float*)d_in[5];
    const float* gnb = (const float*)d_in[6];
    float* out = (float*)d_out;

    size_t smem = sizeof(SmC);
    cudaFuncSetAttribute(fused_kernel, cudaFuncAttributeMaxDynamicSharedMemorySize, (int)smem);
    fused_kernel<<<2048, NTH, smem>>>(x, w1, b1, w3, b3, gnw, gnb, out);
}

// round 5
// speedup vs baseline: 1.5048x; 1.0102x over previous
#include <cuda_runtime.h>
#include <cstdint>
#include <math.h>

#define NCG 8
#define RR 32
#define PHh 34
#define PW 68
#define NTH 512

struct SmC {
    float tile[NCG][PHh][PW];   // padded local tile
    float excol[2][NCG][64];    // partial colsums per rank
    float colm[NCG][64];        // merged colsums
    float exedge[2][NCG];       // rowsum of global row 0 / 63
    float excor[2][NCG][2];     // corners
    float exsg[2][NCG][2];      // gated sum partials [rank][c][half]
    float exsg2[2][NCG][2];
    float rowsum[NCG][RR];
    float sh[NCG][RR];
    float sw[NCG][64];
    float wt[RR * 64];
    float w1s[64];
    float w3s[576];
    float b1s[8], b3s[8], gnws[8], gnbs[8];
    float T[8], S2l[8];
    float Aarr[8], Kpart[8];
    float Weff[72];
};

__device__ __forceinline__ float sigf(float v) {
    return 1.0f / (1.0f + __expf(-v));
}

__device__ __forceinline__ uint32_t s2u(const void* p) {
    uint32_t a;
    asm("{ .reg .u64 t; cvta.to.shared.u64 t, %1; cvt.u32.u64 %0, t; }" : "=r"(a) : "l"(p));
    return a;
}

__device__ __forceinline__ void st_peer(const void* laddr, uint32_t prank, float v) {
    uint32_t la = s2u(laddr);
    uint32_t ra;
    asm volatile("mapa.shared::cluster.u32 %0, %1, %2;" : "=r"(ra) : "r"(la), "r"(prank));
    asm volatile("st.shared::cluster.f32 [%0], %1;" :: "r"(ra), "f"(v) : "memory");
}

#define CLUSTER_SYNC() do { \
    asm volatile("barrier.cluster.arrive.aligned;" ::: "memory"); \
    asm volatile("barrier.cluster.wait.aligned;" ::: "memory"); \
} while (0)

__global__ void __launch_bounds__(NTH, 2) __cluster_dims__(2, 1, 1)
fused_kernel(const float* __restrict__ x,
             const float* __restrict__ w1, const float* __restrict__ b1,
             const float* __restrict__ w3, const float* __restrict__ b3,
             const float* __restrict__ gnw, const float* __restrict__ gnb,
             float* __restrict__ out)
{
    extern __shared__ char smraw[];
    SmC& s = *reinterpret_cast<SmC*>(smraw);
    const int tid = threadIdx.x;
    uint32_t rank;
    asm("mov.u32 %0, %%cluster_ctarank;" : "=r"(rank));
    const uint32_t prank = 1u - rank;
    const long long g = blockIdx.x >> 1;
    const int rbase = (int)rank * RR;
    const float* src = x + g * 32768;
    float* dst = out + g * 32768;
    const float4* src4 = reinterpret_cast<const float4*>(src);

    // ---- phase A: border zeros + params + tile load (+ halo row) ----
    for (int t = tid; t < 8 * 204; t += NTH) {
        int c = t / 204;
        int r = t % 204;
        if (r < 68) {
            int row = (rank == 0) ? 0 : 33;
            s.tile[c][row][r] = 0.f;
        } else {
            int rr2 = r - 68;
            int row = rr2 >> 2;
            int cs = rr2 & 3;
            int col = (cs == 0) ? 0 : (64 + cs);
            s.tile[c][row][col] = 0.f;
        }
    }
    if (tid < 64) s.w1s[tid] = w1[tid];
    if (tid >= 64 && tid < 72) {
        int c = tid - 64;
        s.b1s[c] = b1[c]; s.b3s[c] = b3[c];
        s.gnws[c] = gnw[c]; s.gnbs[c] = gnb[c];
    }
    for (int t = tid; t < 576; t += NTH) s.w3s[t] = w3[t];

    #pragma unroll
    for (int k = 0; k < 8; k++) {
        int l4 = tid + NTH * k;
        int c = l4 >> 9;
        int i = (l4 >> 4) & 31;
        int j4 = (l4 & 15) << 2;
        float4 v = src4[c * 1024 + (rbase + i) * 16 + (j4 >> 2)];
        float* p = &s.tile[c][i + 1][j4 + 1];
        p[0] = v.x; p[1] = v.y; p[2] = v.z; p[3] = v.w;
    }
    if (tid < 128) {
        int c = tid >> 4;
        int j4 = (tid & 15) << 2;
        int grow = (rank == 0) ? 32 : 31;
        int prow = (rank == 0) ? 33 : 0;
        float4 v = src4[c * 1024 + grow * 16 + (j4 >> 2)];
        float* p = &s.tile[c][prow][j4 + 1];
        p[0] = v.x; p[1] = v.y; p[2] = v.z; p[3] = v.w;
    }
    __syncthreads();

    // ---- phase B: rowsums + colsum partials + edges + corners, exchange ----
    #pragma unroll
    for (int t = tid; t < 768; t += NTH) {
        if (t < 256) {
            int c = t >> 5, i = t & 31;
            const float4* rp = reinterpret_cast<const float4*>(&s.tile[c][i + 1][0]);
            float a0 = 0.f, a1 = 0.f;
            #pragma unroll
            for (int q = 0; q < 16; q += 2) {
                float4 v = rp[q];
                a0 += (v.x + v.y) + (v.z + v.w);
                float4 u = rp[q + 1];
                a1 += (u.x + u.y) + (u.z + u.w);
            }
            float4 v = rp[16];
            a0 += (v.x + v.y) + (v.z + v.w);
            float rsum = a0 + a1;
            s.rowsum[c][i] = rsum;
            int edgei = (rank == 0) ? 0 : 31;
            if (i == edgei) {
                s.exedge[rank][c] = rsum;
                st_peer(&s.exedge[rank][c], prank, rsum);
            }
        } else {
            int u = t - 256;
            int c = u >> 6, j = u & 63;
            float a0 = 0.f, a1 = 0.f, a2 = 0.f, a3 = 0.f;
            #pragma unroll
            for (int r = 0; r < 32; r += 4) {
                a0 += s.tile[c][r + 1][j + 1];
                a1 += s.tile[c][r + 2][j + 1];
                a2 += s.tile[c][r + 3][j + 1];
                a3 += s.tile[c][r + 4][j + 1];
            }
            float csum = (a0 + a1) + (a2 + a3);
            s.excol[rank][c][j] = csum;
            st_peer(&s.excol[rank][c][j], prank, csum);
        }
    }
    if (tid < 8) {
        int c = tid;
        float a, b;
        if (rank == 0) { a = s.tile[c][1][1];  b = s.tile[c][1][64]; }
        else           { a = s.tile[c][32][1]; b = s.tile[c][32][64]; }
        s.excor[rank][c][0] = a;
        s.excor[rank][c][1] = b;
        st_peer(&s.excor[rank][c][0], prank, a);
        st_peer(&s.excor[rank][c][1], prank, b);
    }
    CLUSTER_SYNC();

    // ---- phase C: sh (local rows) + sw (merging colsum partials inline) ----
    #pragma unroll
    for (int t = tid; t < 768; t += NTH) {
        const float inv = 1.0f / 64.0f;
        if (t < 256) {
            int o = t >> 5, i = t & 31;
            float acc = s.b1s[o];
            #pragma unroll
            for (int c = 0; c < 8; c++) acc += s.w1s[o * 8 + c] * (s.rowsum[c][i] * inv);
            s.sh[o][i] = sigf(acc);
        } else {
            int u = t - 256;
            int o = u >> 6, j = u & 63;
            float acc = s.b1s[o];
            #pragma unroll
            for (int c = 0; c < 8; c++) {
                float cm = s.excol[0][c][j] + s.excol[1][c][j];
                if (o == 0) s.colm[c][j] = cm;
                acc += s.w1s[o * 8 + c] * (cm * inv);
            }
            s.sw[o][j] = sigf(acc);
        }
    }
    __syncthreads();

    // ---- phase D: gated stats (all warps) + T/S2l (tid<8), exchange ----
    {
        int w = tid >> 5;
        int c = w >> 1;
        int half = w & 1;
        int lane = tid & 31;
        float sw0 = s.sw[c][lane], sw1 = s.sw[c][lane + 32];
        float s0 = 0.f, s1 = 0.f, q0 = 0.f, q1 = 0.f;
        int ibase = half * 16;
        #pragma unroll 4
        for (int r = 0; r < 16; r++) {
            int i = ibase + r;
            float shi = s.sh[c][i];
            float v0 = s.tile[c][i + 1][lane + 1]  * (shi * sw0);
            float v1 = s.tile[c][i + 1][lane + 33] * (shi * sw1);
            s0 += v0; s1 += v1;
            q0 += v0 * v0; q1 += v1 * v1;
        }
        float sum = s0 + s1, sq = q0 + q1;
        #pragma unroll
        for (int off = 16; off; off >>= 1) {
            sum += __shfl_xor_sync(0xffffffffu, sum, off);
            sq  += __shfl_xor_sync(0xffffffffu, sq,  off);
        }
        if (lane == 0) {
            s.exsg[rank][c][half] = sum;  s.exsg2[rank][c][half] = sq;
            st_peer(&s.exsg[rank][c][half],  prank, sum);
            st_peer(&s.exsg2[rank][c][half], prank, sq);
        }
    }
    if (tid < 8) {
        int c = tid;
        float a0 = 0.f, a1 = 0.f, a2 = 0.f, a3 = 0.f;
        #pragma unroll
        for (int j = 0; j < 64; j += 4) {
            a0 += s.colm[c][j];     a1 += s.colm[c][j + 1];
            a2 += s.colm[c][j + 2]; a3 += s.colm[c][j + 3];
        }
        s.T[c] = (a0 + a1) + (a2 + a3);
    }
    __syncthreads();
    if (tid < 8) {
        int c = tid;
        float acc = 0.f;
        #pragma unroll
        for (int ci = 0; ci < 8; ci++) {
            float T   = s.T[ci];
            float r0  = s.exedge[0][ci], r63 = s.exedge[1][ci];
            float c0  = s.colm[ci][0],   c63 = s.colm[ci][63];
            float g00 = s.excor[0][ci][0], g0e = s.excor[0][ci][1];
            float ge0 = s.excor[1][ci][0], gee = s.excor[1][ci][1];
            float Sv[9];
            Sv[0] = T - r63 - c63 + gee;
            Sv[1] = T - r63;
            Sv[2] = T - r63 - c0 + ge0;
            Sv[3] = T - c63;
            Sv[4] = T;
            Sv[5] = T - c0;
            Sv[6] = T - r0 - c63 + g0e;
            Sv[7] = T - r0;
            Sv[8] = T - r0 - c0 + g00;
            const float* wp = &s.w3s[c * 72 + ci * 9];
            #pragma unroll
            for (int t = 0; t < 9; t++) acc += wp[t] * Sv[t];
        }
        s.S2l[c] = acc * (1.0f / 4096.0f) + s.b3s[c];
    }
    CLUSTER_SYNC();

    // ---- phase E: redundant softmaxes in 80 threads -> Weff / Aarr / Kpart ----
    if (tid < 80) {
        float mx1 = -1e30f, mx2 = -1e30f;
        #pragma unroll
        for (int k = 0; k < 8; k++) {
            mx1 = fmaxf(mx1, s.gnbs[k]);
            mx2 = fmaxf(mx2, s.S2l[k]);
        }
        float e1[8], e2[8];
        float d1 = 0.f, d2 = 0.f;
        #pragma unroll
        for (int k = 0; k < 8; k++) {
            e1[k] = __expf(s.gnbs[k] - mx1); d1 += e1[k];
            e2[k] = __expf(s.S2l[k] - mx2);  d2 += e2[k];
        }
        if (tid < 72) {
            int ci = tid / 9, tap = tid % 9;
            float acc = 0.f;
            #pragma unroll
            for (int o = 0; o < 8; o++) acc += e1[o] * s.w3s[o * 72 + ci * 9 + tap];
            s.Weff[tid] = acc / d1;
        } else {
            int c = tid - 72;
            float m = (s.exsg[0][c][0] + s.exsg[0][c][1]
                     + s.exsg[1][c][0] + s.exsg[1][c][1]) * (1.0f / 4096.0f);
            float q = (s.exsg2[0][c][0] + s.exsg2[0][c][1]
                     + s.exsg2[1][c][0] + s.exsg2[1][c][1]) * (1.0f / 4096.0f);
            float rsg = rsqrtf(q - m * m + 1e-5f);
            float x21 = e2[c] / d2;
            float x11 = e1[c] / d1;
            float gr = s.gnws[c] * rsg;
            s.Aarr[c]  = x21 * gr;
            s.Kpart[c] = x21 * (s.gnbs[c] - gr * m) + x11 * s.b3s[c];
        }
    }
    __syncthreads();

    // ---- F1: fused conv(Weff) + gated-norm term -> sigmoid -> wt ----
    {
        int i0 = tid >> 4;             // local output row 0..31
        int j0 = (tid & 15) << 2;      // output cols j0..j0+3
        float basec = ((s.Kpart[0] + s.Kpart[1]) + (s.Kpart[2] + s.Kpart[3]))
                    + ((s.Kpart[4] + s.Kpart[5]) + (s.Kpart[6] + s.Kpart[7]));
        float acc[4];
        #pragma unroll
        for (int p = 0; p < 4; p++) acc[p] = basec;

        #pragma unroll
        for (int ci = 0; ci < 8; ci++) {
            const float* bp = &s.tile[ci][i0][j0];
            float4 ra0 = *(const float4*)(bp);
            float4 rb0 = *(const float4*)(bp + 4);
            float4 ra1 = *(const float4*)(bp + PW);
            float4 rb1 = *(const float4*)(bp + PW + 4);
            float4 ra2 = *(const float4*)(bp + 2 * PW);
            float4 rb2 = *(const float4*)(bp + 2 * PW + 4);
            float w0[8]  = {ra0.x, ra0.y, ra0.z, ra0.w, rb0.x, rb0.y, rb0.z, rb0.w};
            float w1r[8] = {ra1.x, ra1.y, ra1.z, ra1.w, rb1.x, rb1.y, rb1.z, rb1.w};
            float w2r[8] = {ra2.x, ra2.y, ra2.z, ra2.w, rb2.x, rb2.y, rb2.z, rb2.w};
            const float* wc = &s.Weff[ci * 9];
            float c0w = wc[0], c1w = wc[1], c2w = wc[2];
            float c3w = wc[3], c4w = wc[4], c5w = wc[5];
            float c6w = wc[6], c7w = wc[7], c8w = wc[8];
            float coef = s.Aarr[ci] * s.sh[ci][i0];
            float4 swv = *(const float4*)&s.sw[ci][j0];
            float swp[4] = {swv.x, swv.y, swv.z, swv.w};
            #pragma unroll
            for (int p = 0; p < 4; p++) {
                acc[p] += c0w*w0[p]  + c1w*w0[p+1]  + c2w*w0[p+2]
                        + c3w*w1r[p] + c4w*w1r[p+1] + c5w*w1r[p+2]
                        + c6w*w2r[p] + c7w*w2r[p+1] + c8w*w2r[p+2]
                        + coef * swp[p] * w1r[p+1];
            }
        }
        *(float4*)&s.wt[i0 * 64 + j0] =
            make_float4(sigf(acc[0]), sigf(acc[1]), sigf(acc[2]), sigf(acc[3]));
    }
    __syncthreads();

    // ---- F2: out = gx * weights (float4 stores) ----
    #pragma unroll
    for (int k = 0; k < 8; k++) {
        int l4 = tid + NTH * k;
        int c = l4 >> 9;
        int i = (l4 >> 4) & 31;
        int j4 = (l4 & 15) << 2;
        float4 wv = *(const float4*)&s.wt[i * 64 + j4];
        const float* p = &s.tile[c][i + 1][j4 + 1];
        float4 o4 = make_float4(p[0] * wv.x, p[1] * wv.y, p[2] * wv.z, p[3] * wv.w);
        *reinterpret_cast<float4*>(&dst[c * 4096 + (rbase + i) * 64 + j4]) = o4;
    }
}

extern "C" void kernel_launch(void* const* d_in, const int* in_sizes, int n_in,
                              void* d_out, int out_size) {
    (void)in_sizes; (void)n_in; (void)out_size;
    const float* x   = (const float*)d_in[0];
    const float* w1  = (const float*)d_in[1];
    const float* b1  = (const float*)d_in[2];
    const float* w3  = (const float*)d_in[3];
    const float* b3  = (const float*)d_in[4];
    const float* gnw = (const float*)d_in[5];
    const float* gnb = (const float*)d_in[6];
    float* out = (float*)d_out;

    size_t smem = sizeof(SmC);
    cudaFuncSetAttribute(fused_kernel, cudaFuncAttributeMaxDynamicSharedMemorySize, (int)smem);
    fused_kernel<<<2048, NTH, smem>>>(x, w1, b1, w3, b3, gnw, gnb, out);
}

// round 6
// speedup vs baseline: 1.5917x; 1.0577x over previous
#include <cuda_runtime.h>
#include <cuda_fp16.h>
#include <cstdint>
#include <math.h>

#define PWH 72
#define NTH 512

struct SmC {
    __half tile[8][34][PWH];   // fp16 padded tile; interior at rows 1..32, cols 2..65
    float excol[2][8][64];
    float colm[8][64];
    float exedge[2][8];
    float excor[2][8][2];
    float exsg[2][8][2];
    float exsg2[2][8][2];
    float rowsum[8][32];
    float sh[8][32];
    float sw[8][64];
    float wt[2048];
    float w1s[64];
    float w3s[576];
    float b1s[8], b3s[8], gnws[8], gnbs[8];
    float T[8], S2l[8];
    float Aarr[8], Kpart[8];
    float Weff[72];
};

__device__ __forceinline__ float sigf(float v) {
    return 1.0f / (1.0f + __expf(-v));
}

__device__ __forceinline__ uint32_t s2u(const void* p) {
    uint32_t a;
    asm("{ .reg .u64 t; cvta.to.shared.u64 t, %1; cvt.u32.u64 %0, t; }" : "=r"(a) : "l"(p));
    return a;
}

__device__ __forceinline__ void st_peer(const void* laddr, uint32_t prank, float v) {
    uint32_t la = s2u(laddr);
    uint32_t ra;
    asm volatile("mapa.shared::cluster.u32 %0, %1, %2;" : "=r"(ra) : "r"(la), "r"(prank));
    asm volatile("st.shared::cluster.f32 [%0], %1;" :: "r"(ra), "f"(v) : "memory");
}

#define CLUSTER_SYNC() do { \
    asm volatile("barrier.cluster.arrive.aligned;" ::: "memory"); \
    asm volatile("barrier.cluster.wait.aligned;" ::: "memory"); \
} while (0)

// load 12 consecutive padded halfs (16B-aligned) -> 12 floats
__device__ __forceinline__ void ld12(const __half* p, float* w) {
    uint4 a = *(const uint4*)p;
    uint2 b = *(const uint2*)(p + 8);
    float2 f;
    f = __half22float2(*(__half2*)&a.x); w[0] = f.x;  w[1] = f.y;
    f = __half22float2(*(__half2*)&a.y); w[2] = f.x;  w[3] = f.y;
    f = __half22float2(*(__half2*)&a.z); w[4] = f.x;  w[5] = f.y;
    f = __half22float2(*(__half2*)&a.w); w[6] = f.x;  w[7] = f.y;
    f = __half22float2(*(__half2*)&b.x); w[8] = f.x;  w[9] = f.y;
    f = __half22float2(*(__half2*)&b.y); w[10] = f.x; w[11] = f.y;
}

__global__ void __launch_bounds__(NTH, 2) __cluster_dims__(2, 1, 1)
fused_kernel(const float* __restrict__ x,
             const float* __restrict__ w1, const float* __restrict__ b1,
             const float* __restrict__ w3, const float* __restrict__ b3,
             const float* __restrict__ gnw, const float* __restrict__ gnb,
             float* __restrict__ out)
{
    extern __shared__ char smraw[];
    SmC& s = *reinterpret_cast<SmC*>(smraw);
    const int tid = threadIdx.x;
    uint32_t rank;
    asm("mov.u32 %0, %%cluster_ctarank;" : "=r"(rank));
    const uint32_t prank = 1u - rank;
    const long long g = blockIdx.x >> 1;
    const int rbase = (int)rank * 32;
    const float* src = x + g * 32768;
    float* dst = out + g * 32768;
    const float4* src4 = reinterpret_cast<const float4*>(src);

    // ---- phase A: borders + params + interior load (fp16 STS) + halo row ----
    {
        const __half hz = __float2half(0.f);
        int outer = (rank == 0) ? 0 : 33;
        for (int t = tid; t < 8 * 408; t += NTH) {
            int c = t / 408;
            int u = t % 408;
            if (u < 72) {
                s.tile[c][outer][u] = hz;
            } else {
                int u2 = u - 72;             // 0..335
                int r = u2 >> 3;             // 0..32
                int row = (rank == 0) ? (r + 1) : r;
                int m = u2 & 7;
                int col = (m < 2) ? m : (64 + m);
                s.tile[c][row][col] = hz;
            }
        }
    }
    if (tid < 64) s.w1s[tid] = w1[tid];
    if (tid >= 64 && tid < 72) {
        int c = tid - 64;
        s.b1s[c] = b1[c]; s.b3s[c] = b3[c];
        s.gnws[c] = gnw[c]; s.gnbs[c] = gnb[c];
    }
    for (int t = tid; t < 576; t += NTH) s.w3s[t] = w3[t];

    {
        int i = (tid >> 4) & 31;
        int j4 = (tid & 15) << 2;
        #pragma unroll
        for (int c = 0; c < 8; c++) {
            float4 v = src4[c * 1024 + (rbase + i) * 16 + (j4 >> 2)];
            __half2* p = (__half2*)&s.tile[c][i + 1][j4 + 2];
            p[0] = __floats2half2_rn(v.x, v.y);
            p[1] = __floats2half2_rn(v.z, v.w);
        }
    }
    if (tid < 128) {
        int c = tid >> 4;
        int j4 = (tid & 15) << 2;
        int grow = (rank == 0) ? 32 : 31;
        int prow = (rank == 0) ? 33 : 0;
        float4 v = src4[c * 1024 + grow * 16 + (j4 >> 2)];
        __half2* p = (__half2*)&s.tile[c][prow][j4 + 2];
        p[0] = __floats2half2_rn(v.x, v.y);
        p[1] = __floats2half2_rn(v.z, v.w);
    }
    __syncthreads();

    // ---- phase B: rowsums + colsum partials + edges + corners, exchange ----
    #pragma unroll
    for (int t = tid; t < 768; t += NTH) {
        if (t < 256) {
            int c = t >> 5, i = t & 31;
            const uint4* rp = reinterpret_cast<const uint4*>(&s.tile[c][i + 1][0]);
            float a0 = 0.f, a1 = 0.f;
            #pragma unroll
            for (int q = 0; q < 9; q++) {
                uint4 u = rp[q];
                float2 f0 = __half22float2(*(__half2*)&u.x);
                float2 f1 = __half22float2(*(__half2*)&u.y);
                float2 f2 = __half22float2(*(__half2*)&u.z);
                float2 f3 = __half22float2(*(__half2*)&u.w);
                a0 += (f0.x + f0.y) + (f1.x + f1.y);
                a1 += (f2.x + f2.y) + (f3.x + f3.y);
            }
            float rsum = a0 + a1;
            s.rowsum[c][i] = rsum;
            int edgei = (rank == 0) ? 0 : 31;
            if (i == edgei) {
                s.exedge[rank][c] = rsum;
                st_peer(&s.exedge[rank][c], prank, rsum);
            }
        } else {
            int u = t - 256;
            int c = u >> 6, j = u & 63;
            float a0 = 0.f, a1 = 0.f, a2 = 0.f, a3 = 0.f;
            #pragma unroll
            for (int r = 0; r < 32; r += 4) {
                a0 += __half2float(s.tile[c][r + 1][j + 2]);
                a1 += __half2float(s.tile[c][r + 2][j + 2]);
                a2 += __half2float(s.tile[c][r + 3][j + 2]);
                a3 += __half2float(s.tile[c][r + 4][j + 2]);
            }
            float csum = (a0 + a1) + (a2 + a3);
            s.excol[rank][c][j] = csum;
            st_peer(&s.excol[rank][c][j], prank, csum);
        }
    }
    if (tid < 8) {
        int c = tid;
        float a, b;
        if (rank == 0) { a = __half2float(s.tile[c][1][2]);  b = __half2float(s.tile[c][1][65]); }
        else           { a = __half2float(s.tile[c][32][2]); b = __half2float(s.tile[c][32][65]); }
        s.excor[rank][c][0] = a;
        s.excor[rank][c][1] = b;
        st_peer(&s.excor[rank][c][0], prank, a);
        st_peer(&s.excor[rank][c][1], prank, b);
    }
    CLUSTER_SYNC();

    // ---- phase C: sh (local rows) + sw (merging colsum partials inline) ----
    #pragma unroll
    for (int t = tid; t < 768; t += NTH) {
        const float inv = 1.0f / 64.0f;
        if (t < 256) {
            int o = t >> 5, i = t & 31;
            float acc = s.b1s[o];
            #pragma unroll
            for (int c = 0; c < 8; c++) acc += s.w1s[o * 8 + c] * (s.rowsum[c][i] * inv);
            s.sh[o][i] = sigf(acc);
        } else {
            int u = t - 256;
            int o = u >> 6, j = u & 63;
            float acc = s.b1s[o];
            #pragma unroll
            for (int c = 0; c < 8; c++) {
                float cm = s.excol[0][c][j] + s.excol[1][c][j];
                if (o == 0) s.colm[c][j] = cm;
                acc += s.w1s[o * 8 + c] * (cm * inv);
            }
            s.sw[o][j] = sigf(acc);
        }
    }
    __syncthreads();

    // ---- phase D: gated stats + T/S2l, exchange ----
    {
        int w = tid >> 5;
        int c = w >> 1;
        int half = w & 1;
        int lane = tid & 31;
        float sw0 = s.sw[c][lane], sw1 = s.sw[c][lane + 32];
        float s0 = 0.f, s1 = 0.f, q0 = 0.f, q1 = 0.f;
        int ibase = half * 16;
        #pragma unroll 4
        for (int r = 0; r < 16; r++) {
            int i = ibase + r;
            float shi = s.sh[c][i];
            float g0 = __half2float(s.tile[c][i + 1][lane + 2]);
            float g1 = __half2float(s.tile[c][i + 1][lane + 34]);
            float v0 = g0 * (shi * sw0);
            float v1 = g1 * (shi * sw1);
            s0 += v0; s1 += v1;
            q0 += v0 * v0; q1 += v1 * v1;
        }
        float sum = s0 + s1, sq = q0 + q1;
        #pragma unroll
        for (int off = 16; off; off >>= 1) {
            sum += __shfl_xor_sync(0xffffffffu, sum, off);
            sq  += __shfl_xor_sync(0xffffffffu, sq,  off);
        }
        if (lane == 0) {
            s.exsg[rank][c][half] = sum;  s.exsg2[rank][c][half] = sq;
            st_peer(&s.exsg[rank][c][half],  prank, sum);
            st_peer(&s.exsg2[rank][c][half], prank, sq);
        }
    }
    if (tid < 8) {
        int c = tid;
        float a0 = 0.f, a1 = 0.f, a2 = 0.f, a3 = 0.f;
        #pragma unroll
        for (int j = 0; j < 64; j += 4) {
            a0 += s.colm[c][j];     a1 += s.colm[c][j + 1];
            a2 += s.colm[c][j + 2]; a3 += s.colm[c][j + 3];
        }
        s.T[c] = (a0 + a1) + (a2 + a3);
    }
    __syncthreads();
    if (tid < 8) {
        int c = tid;
        float acc = 0.f;
        #pragma unroll
        for (int ci = 0; ci < 8; ci++) {
            float T   = s.T[ci];
            float r0  = s.exedge[0][ci], r63 = s.exedge[1][ci];
            float c0  = s.colm[ci][0],   c63 = s.colm[ci][63];
            float g00 = s.excor[0][ci][0], g0e = s.excor[0][ci][1];
            float ge0 = s.excor[1][ci][0], gee = s.excor[1][ci][1];
            float Sv[9];
            Sv[0] = T - r63 - c63 + gee;
            Sv[1] = T - r63;
            Sv[2] = T - r63 - c0 + ge0;
            Sv[3] = T - c63;
            Sv[4] = T;
            Sv[5] = T - c0;
            Sv[6] = T - r0 - c63 + g0e;
            Sv[7] = T - r0;
            Sv[8] = T - r0 - c0 + g00;
            const float* wp = &s.w3s[c * 72 + ci * 9];
            #pragma unroll
            for (int t = 0; t < 9; t++) acc += wp[t] * Sv[t];
        }
        s.S2l[c] = acc * (1.0f / 4096.0f) + s.b3s[c];
    }
    CLUSTER_SYNC();

    // ---- phase E: redundant softmaxes -> Weff / Aarr / Kpart ----
    if (tid < 80) {
        float mx1 = -1e30f, mx2 = -1e30f;
        #pragma unroll
        for (int k = 0; k < 8; k++) {
            mx1 = fmaxf(mx1, s.gnbs[k]);
            mx2 = fmaxf(mx2, s.S2l[k]);
        }
        float e1[8], e2[8];
        float d1 = 0.f, d2 = 0.f;
        #pragma unroll
        for (int k = 0; k < 8; k++) {
            e1[k] = __expf(s.gnbs[k] - mx1); d1 += e1[k];
            e2[k] = __expf(s.S2l[k] - mx2);  d2 += e2[k];
        }
        if (tid < 72) {
            int ci = tid / 9, tap = tid % 9;
            float acc = 0.f;
            #pragma unroll
            for (int o = 0; o < 8; o++) acc += e1[o] * s.w3s[o * 72 + ci * 9 + tap];
            s.Weff[tid] = acc / d1;
        } else {
            int c = tid - 72;
            float m = (s.exsg[0][c][0] + s.exsg[0][c][1]
                     + s.exsg[1][c][0] + s.exsg[1][c][1]) * (1.0f / 4096.0f);
            float q = (s.exsg2[0][c][0] + s.exsg2[0][c][1]
                     + s.exsg2[1][c][0] + s.exsg2[1][c][1]) * (1.0f / 4096.0f);
            float rsg = rsqrtf(q - m * m + 1e-5f);
            float x21 = e2[c] / d2;
            float x11 = e1[c] / d1;
            float gr = s.gnws[c] * rsg;
            s.Aarr[c]  = x21 * gr;
            s.Kpart[c] = x21 * (s.gnbs[c] - gr * m) + x11 * s.b3s[c];
        }
    }
    __syncthreads();

    // ---- F1: fused conv + gated-norm -> sigmoid -> wt (1 row x 8 cols/thread) ----
    if (tid < 256) {
        int i0 = tid >> 3;            // local output row 0..31
        int j0 = (tid & 7) << 3;      // output cols j0..j0+7
        float basec = ((s.Kpart[0] + s.Kpart[1]) + (s.Kpart[2] + s.Kpart[3]))
                    + ((s.Kpart[4] + s.Kpart[5]) + (s.Kpart[6] + s.Kpart[7]));
        float acc[8];
        #pragma unroll
        for (int p = 0; p < 8; p++) acc[p] = basec;

        #pragma unroll
        for (int ci = 0; ci < 8; ci++) {
            const float* wc = &s.Weff[ci * 9];
            float c0w = wc[0], c1w = wc[1], c2w = wc[2];
            float c3w = wc[3], c4w = wc[4], c5w = wc[5];
            float c6w = wc[6], c7w = wc[7], c8w = wc[8];
            float coef = s.Aarr[ci] * s.sh[ci][i0];
            float4 swa = *(const float4*)&s.sw[ci][j0];
            float4 swb = *(const float4*)&s.sw[ci][j0 + 4];
            float swp[8] = {swa.x, swa.y, swa.z, swa.w, swb.x, swb.y, swb.z, swb.w};
            float w[12];
            // top row (padded i0 = interior i0-1)
            ld12(&s.tile[ci][i0][j0], w);
            #pragma unroll
            for (int p = 0; p < 8; p++)
                acc[p] += c0w * w[p + 1] + c1w * w[p + 2] + c2w * w[p + 3];
            // mid row (interior i0): conv mid taps + gating center
            ld12(&s.tile[ci][i0 + 1][j0], w);
            #pragma unroll
            for (int p = 0; p < 8; p++)
                acc[p] += c3w * w[p + 1] + c4w * w[p + 2] + c5w * w[p + 3]
                        + coef * swp[p] * w[p + 2];
            // bottom row (interior i0+1)
            ld12(&s.tile[ci][i0 + 2][j0], w);
            #pragma unroll
            for (int p = 0; p < 8; p++)
                acc[p] += c6w * w[p + 1] + c7w * w[p + 2] + c8w * w[p + 3];
        }
        *(float4*)&s.wt[i0 * 64 + j0] =
            make_float4(sigf(acc[0]), sigf(acc[1]), sigf(acc[2]), sigf(acc[3]));
        *(float4*)&s.wt[i0 * 64 + j0 + 4] =
            make_float4(sigf(acc[4]), sigf(acc[5]), sigf(acc[6]), sigf(acc[7]));
    }
    __syncthreads();

    // ---- F2: out = gx(fp32 from L2) * weights ----
    {
        int i = (tid >> 4) & 31;
        int j4 = (tid & 15) << 2;
        float4 wv = *(const float4*)&s.wt[i * 64 + j4];
        #pragma unroll
        for (int c = 0; c < 8; c++) {
            float4 v = src4[c * 1024 + (rbase + i) * 16 + (j4 >> 2)];
            float4 o4 = make_float4(v.x * wv.x, v.y * wv.y, v.z * wv.z, v.w * wv.w);
            *reinterpret_cast<float4*>(&dst[c * 4096 + (rbase + i) * 64 + j4]) = o4;
        }
    }
}

extern "C" void kernel_launch(void* const* d_in, const int* in_sizes, int n_in,
                              void* d_out, int out_size) {
    (void)in_sizes; (void)n_in; (void)out_size;
    const float* x   = (const float*)d_in[0];
    const float* w1  = (const float*)d_in[1];
    const float* b1  = (const float*)d_in[2];
    const float* w3  = (const float*)d_in[3];
    const float* b3  = (const float*)d_in[4];
    const float* gnw = (const float*)d_in[5];
    const float* gnb = (const float*)d_in[6];
    float* out = (float*)d_out;

    size_t smem = sizeof(SmC);
    cudaFuncSetAttribute(fused_kernel, cudaFuncAttributeMaxDynamicSharedMemorySize, (int)smem);
    fused_kernel<<<2048, NTH, smem>>>(x, w1, b1, w3, b3, gnw, gnb, out);
}

// round 7
// speedup vs baseline: 1.6696x; 1.0489x over previous
#include <cuda_runtime.h>
#include <cuda_fp16.h>
#include <cstdint>
#include <math.h>

#define PWH 72
#define NTH 512

struct SmC {
    __half tile[8][34][PWH];   // fp16 padded tile; interior rows 1..32, cols 2..65
    float excol[2][8][64];
    float colm[8][64];
    float exedge[2][8];
    float excor[2][8][2];
    float exsg[2][8][2];
    float exsg2[2][8][2];
    float rowsum[8][32];
    float sh[8][32];
    float sw[8][64];
    float accp[2][32][64];     // F1 partial sums (ci 0-3 / ci 4-7)
    float w1s[64];
    float w3s[576];
    float b1s[8], b3s[8], gnws[8], gnbs[8];
    float T[8], S2l[8];
    float Aarr[8], Kpart[8];
    float Weff[72];
};

__device__ __forceinline__ float sigf(float v) {
    return 1.0f / (1.0f + __expf(-v));
}

__device__ __forceinline__ uint32_t s2u(const void* p) {
    uint32_t a;
    asm("{ .reg .u64 t; cvta.to.shared.u64 t, %1; cvt.u32.u64 %0, t; }" : "=r"(a) : "l"(p));
    return a;
}

__device__ __forceinline__ void st_peer(const void* laddr, uint32_t prank, float v) {
    uint32_t la = s2u(laddr);
    uint32_t ra;
    asm volatile("mapa.shared::cluster.u32 %0, %1, %2;" : "=r"(ra) : "r"(la), "r"(prank));
    asm volatile("st.shared::cluster.f32 [%0], %1;" :: "r"(ra), "f"(v) : "memory");
}

#define CLUSTER_SYNC() do { \
    asm volatile("barrier.cluster.arrive.aligned;" ::: "memory"); \
    asm volatile("barrier.cluster.wait.aligned;" ::: "memory"); \
} while (0)

// load 12 consecutive padded halfs (16B-aligned) -> 12 floats
__device__ __forceinline__ void ld12(const __half* p, float* w) {
    uint4 a = *(const uint4*)p;
    uint2 b = *(const uint2*)(p + 8);
    float2 f;
    f = __half22float2(*(__half2*)&a.x); w[0] = f.x;  w[1] = f.y;
    f = __half22float2(*(__half2*)&a.y); w[2] = f.x;  w[3] = f.y;
    f = __half22float2(*(__half2*)&a.z); w[4] = f.x;  w[5] = f.y;
    f = __half22float2(*(__half2*)&a.w); w[6] = f.x;  w[7] = f.y;
    f = __half22float2(*(__half2*)&b.x); w[8] = f.x;  w[9] = f.y;
    f = __half22float2(*(__half2*)&b.y); w[10] = f.x; w[11] = f.y;
}

__global__ void __launch_bounds__(NTH, 2) __cluster_dims__(2, 1, 1)
fused_kernel(const float* __restrict__ x,
             const float* __restrict__ w1, const float* __restrict__ b1,
             const float* __restrict__ w3, const float* __restrict__ b3,
             const float* __restrict__ gnw, const float* __restrict__ gnb,
             float* __restrict__ out)
{
    extern __shared__ char smraw[];
    SmC& s = *reinterpret_cast<SmC*>(smraw);
    const int tid = threadIdx.x;
    uint32_t rank;
    asm("mov.u32 %0, %%cluster_ctarank;" : "=r"(rank));
    const uint32_t prank = 1u - rank;
    const long long g = blockIdx.x >> 1;
    const int rbase = (int)rank * 32;
    const float* src = x + g * 32768;
    float* dst = out + g * 32768;
    const float4* src4 = reinterpret_cast<const float4*>(src);

    // ---- phase A: borders + params + interior load (fp16 STS) + halo row ----
    {
        const __half hz = __float2half(0.f);
        int outer = (rank == 0) ? 0 : 33;
        for (int t = tid; t < 8 * 408; t += NTH) {
            int c = t / 408;
            int u = t % 408;
            if (u < 72) {
                s.tile[c][outer][u] = hz;
            } else {
                int u2 = u - 72;
                int r = u2 >> 3;
                int row = (rank == 0) ? (r + 1) : r;
                int m = u2 & 7;
                int col = (m < 2) ? m : (64 + m);
                s.tile[c][row][col] = hz;
            }
        }
    }
    if (tid < 64) s.w1s[tid] = w1[tid];
    if (tid >= 64 && tid < 72) {
        int c = tid - 64;
        s.b1s[c] = b1[c]; s.b3s[c] = b3[c];
        s.gnws[c] = gnw[c]; s.gnbs[c] = gnb[c];
    }
    for (int t = tid; t < 576; t += NTH) s.w3s[t] = w3[t];

    {
        int i = (tid >> 4) & 31;
        int j4 = (tid & 15) << 2;
        #pragma unroll
        for (int c = 0; c < 8; c++) {
            float4 v = src4[c * 1024 + (rbase + i) * 16 + (j4 >> 2)];
            __half2* p = (__half2*)&s.tile[c][i + 1][j4 + 2];
            p[0] = __floats2half2_rn(v.x, v.y);
            p[1] = __floats2half2_rn(v.z, v.w);
        }
    }
    if (tid < 128) {
        int c = tid >> 4;
        int j4 = (tid & 15) << 2;
        int grow = (rank == 0) ? 32 : 31;
        int prow = (rank == 0) ? 33 : 0;
        float4 v = src4[c * 1024 + grow * 16 + (j4 >> 2)];
        __half2* p = (__half2*)&s.tile[c][prow][j4 + 2];
        p[0] = __floats2half2_rn(v.x, v.y);
        p[1] = __floats2half2_rn(v.z, v.w);
    }
    __syncthreads();

    // ---- phase B: rowsums + colsum partials + edges + corners, exchange ----
    #pragma unroll
    for (int t = tid; t < 768; t += NTH) {
        if (t < 256) {
            int c = t >> 5, i = t & 31;
            const uint4* rp = reinterpret_cast<const uint4*>(&s.tile[c][i + 1][0]);
            float a0 = 0.f, a1 = 0.f;
            #pragma unroll
            for (int q = 0; q < 9; q++) {
                uint4 u = rp[q];
                float2 f0 = __half22float2(*(__half2*)&u.x);
                float2 f1 = __half22float2(*(__half2*)&u.y);
                float2 f2 = __half22float2(*(__half2*)&u.z);
                float2 f3 = __half22float2(*(__half2*)&u.w);
                a0 += (f0.x + f0.y) + (f1.x + f1.y);
                a1 += (f2.x + f2.y) + (f3.x + f3.y);
            }
            float rsum = a0 + a1;
            s.rowsum[c][i] = rsum;
            int edgei = (rank == 0) ? 0 : 31;
            if (i == edgei) {
                s.exedge[rank][c] = rsum;
                st_peer(&s.exedge[rank][c], prank, rsum);
            }
        } else {
            int u = t - 256;
            int c = u >> 6, j = u & 63;
            float a0 = 0.f, a1 = 0.f, a2 = 0.f, a3 = 0.f;
            #pragma unroll
            for (int r = 0; r < 32; r += 4) {
                a0 += __half2float(s.tile[c][r + 1][j + 2]);
                a1 += __half2float(s.tile[c][r + 2][j + 2]);
                a2 += __half2float(s.tile[c][r + 3][j + 2]);
                a3 += __half2float(s.tile[c][r + 4][j + 2]);
            }
            float csum = (a0 + a1) + (a2 + a3);
            s.excol[rank][c][j] = csum;
            st_peer(&s.excol[rank][c][j], prank, csum);
        }
    }
    if (tid < 8) {
        int c = tid;
        float a, b;
        if (rank == 0) { a = __half2float(s.tile[c][1][2]);  b = __half2float(s.tile[c][1][65]); }
        else           { a = __half2float(s.tile[c][32][2]); b = __half2float(s.tile[c][32][65]); }
        s.excor[rank][c][0] = a;
        s.excor[rank][c][1] = b;
        st_peer(&s.excor[rank][c][0], prank, a);
        st_peer(&s.excor[rank][c][1], prank, b);
    }
    CLUSTER_SYNC();

    // ---- phase C: sh (local rows) + sw (merging colsum partials inline) ----
    #pragma unroll
    for (int t = tid; t < 768; t += NTH) {
        const float inv = 1.0f / 64.0f;
        if (t < 256) {
            int o = t >> 5, i = t & 31;
            float acc = s.b1s[o];
            #pragma unroll
            for (int c = 0; c < 8; c++) acc += s.w1s[o * 8 + c] * (s.rowsum[c][i] * inv);
            s.sh[o][i] = sigf(acc);
        } else {
            int u = t - 256;
            int o = u >> 6, j = u & 63;
            float acc = s.b1s[o];
            #pragma unroll
            for (int c = 0; c < 8; c++) {
                float cm = s.excol[0][c][j] + s.excol[1][c][j];
                if (o == 0) s.colm[c][j] = cm;
                acc += s.w1s[o * 8 + c] * (cm * inv);
            }
            s.sw[o][j] = sigf(acc);
        }
    }
    __syncthreads();

    // ---- phase D: gated stats + T/S2l, exchange ----
    {
        int w = tid >> 5;
        int c = w >> 1;
        int half = w & 1;
        int lane = tid & 31;
        float sw0 = s.sw[c][lane], sw1 = s.sw[c][lane + 32];
        float s0 = 0.f, s1 = 0.f, q0 = 0.f, q1 = 0.f;
        int ibase = half * 16;
        #pragma unroll 4
        for (int r = 0; r < 16; r++) {
            int i = ibase + r;
            float shi = s.sh[c][i];
            float g0 = __half2float(s.tile[c][i + 1][lane + 2]);
            float g1 = __half2float(s.tile[c][i + 1][lane + 34]);
            float v0 = g0 * (shi * sw0);
            float v1 = g1 * (shi * sw1);
            s0 += v0; s1 += v1;
            q0 += v0 * v0; q1 += v1 * v1;
        }
        float sum = s0 + s1, sq = q0 + q1;
        #pragma unroll
        for (int off = 16; off; off >>= 1) {
            sum += __shfl_xor_sync(0xffffffffu, sum, off);
            sq  += __shfl_xor_sync(0xffffffffu, sq,  off);
        }
        if (lane == 0) {
            s.exsg[rank][c][half] = sum;  s.exsg2[rank][c][half] = sq;
            st_peer(&s.exsg[rank][c][half],  prank, sum);
            st_peer(&s.exsg2[rank][c][half], prank, sq);
        }
    }
    if (tid < 8) {
        int c = tid;
        float a0 = 0.f, a1 = 0.f, a2 = 0.f, a3 = 0.f;
        #pragma unroll
        for (int j = 0; j < 64; j += 4) {
            a0 += s.colm[c][j];     a1 += s.colm[c][j + 1];
            a2 += s.colm[c][j + 2]; a3 += s.colm[c][j + 3];
        }
        s.T[c] = (a0 + a1) + (a2 + a3);
    }
    __syncthreads();
    if (tid < 8) {
        int c = tid;
        float acc = 0.f;
        #pragma unroll
        for (int ci = 0; ci < 8; ci++) {
            float T   = s.T[ci];
            float r0  = s.exedge[0][ci], r63 = s.exedge[1][ci];
            float c0  = s.colm[ci][0],   c63 = s.colm[ci][63];
            float g00 = s.excor[0][ci][0], g0e = s.excor[0][ci][1];
            float ge0 = s.excor[1][ci][0], gee = s.excor[1][ci][1];
            float Sv[9];
            Sv[0] = T - r63 - c63 + gee;
            Sv[1] = T - r63;
            Sv[2] = T - r63 - c0 + ge0;
            Sv[3] = T - c63;
            Sv[4] = T;
            Sv[5] = T - c0;
            Sv[6] = T - r0 - c63 + g0e;
            Sv[7] = T - r0;
            Sv[8] = T - r0 - c0 + g00;
            const float* wp = &s.w3s[c * 72 + ci * 9];
            #pragma unroll
            for (int t = 0; t < 9; t++) acc += wp[t] * Sv[t];
        }
        s.S2l[c] = acc * (1.0f / 4096.0f) + s.b3s[c];
    }
    CLUSTER_SYNC();

    // ---- phase E: redundant softmaxes -> Weff / Aarr / Kpart ----
    if (tid < 80) {
        float mx1 = -1e30f, mx2 = -1e30f;
        #pragma unroll
        for (int k = 0; k < 8; k++) {
            mx1 = fmaxf(mx1, s.gnbs[k]);
            mx2 = fmaxf(mx2, s.S2l[k]);
        }
        float e1[8], e2[8];
        float d1 = 0.f, d2 = 0.f;
        #pragma unroll
        for (int k = 0; k < 8; k++) {
            e1[k] = __expf(s.gnbs[k] - mx1); d1 += e1[k];
            e2[k] = __expf(s.S2l[k] - mx2);  d2 += e2[k];
        }
        if (tid < 72) {
            int ci = tid / 9, tap = tid % 9;
            float acc = 0.f;
            #pragma unroll
            for (int o = 0; o < 8; o++) acc += e1[o] * s.w3s[o * 72 + ci * 9 + tap];
            s.Weff[tid] = acc / d1;
        } else {
            int c = tid - 72;
            float m = (s.exsg[0][c][0] + s.exsg[0][c][1]
                     + s.exsg[1][c][0] + s.exsg[1][c][1]) * (1.0f / 4096.0f);
            float q = (s.exsg2[0][c][0] + s.exsg2[0][c][1]
                     + s.exsg2[1][c][0] + s.exsg2[1][c][1]) * (1.0f / 4096.0f);
            float rsg = rsqrtf(q - m * m + 1e-5f);
            float x21 = e2[c] / d2;
            float x11 = e1[c] / d1;
            float gr = s.gnws[c] * rsg;
            s.Aarr[c]  = x21 * gr;
            s.Kpart[c] = x21 * (s.gnbs[c] - gr * m) + x11 * s.b3s[c];
        }
    }
    __syncthreads();

    // ---- F1: fused conv + gated-norm, split over ci halves (all 512 threads) ----
    {
        int half = tid >> 8;             // 0: ci 0-3, 1: ci 4-7
        int unit = tid & 255;
        int i0 = unit >> 3;              // local output row 0..31
        int j0 = (unit & 7) << 3;        // output cols j0..j0+7
        int cibase = half << 2;
        float acc[8];
        float init = 0.f;
        if (half == 0) {
            init = ((s.Kpart[0] + s.Kpart[1]) + (s.Kpart[2] + s.Kpart[3]))
                 + ((s.Kpart[4] + s.Kpart[5]) + (s.Kpart[6] + s.Kpart[7]));
        }
        #pragma unroll
        for (int p = 0; p < 8; p++) acc[p] = init;

        #pragma unroll
        for (int cq = 0; cq < 4; cq++) {
            int ci = cibase + cq;
            const float* wc = &s.Weff[ci * 9];
            float c0w = wc[0], c1w = wc[1], c2w = wc[2];
            float c3w = wc[3], c4w = wc[4], c5w = wc[5];
            float c6w = wc[6], c7w = wc[7], c8w = wc[8];
            float coef = s.Aarr[ci] * s.sh[ci][i0];
            float4 swa = *(const float4*)&s.sw[ci][j0];
            float4 swb = *(const float4*)&s.sw[ci][j0 + 4];
            float swp[8] = {swa.x, swa.y, swa.z, swa.w, swb.x, swb.y, swb.z, swb.w};
            float w[12];
            ld12(&s.tile[ci][i0][j0], w);
            #pragma unroll
            for (int p = 0; p < 8; p++)
                acc[p] += c0w * w[p + 1] + c1w * w[p + 2] + c2w * w[p + 3];
            ld12(&s.tile[ci][i0 + 1][j0], w);
            #pragma unroll
            for (int p = 0; p < 8; p++)
                acc[p] += c3w * w[p + 1] + c4w * w[p + 2] + c5w * w[p + 3]
                        + coef * swp[p] * w[p + 2];
            ld12(&s.tile[ci][i0 + 2][j0], w);
            #pragma unroll
            for (int p = 0; p < 8; p++)
                acc[p] += c6w * w[p + 1] + c7w * w[p + 2] + c8w * w[p + 3];
        }
        *(float4*)&s.accp[half][i0][j0] =
            make_float4(acc[0], acc[1], acc[2], acc[3]);
        *(float4*)&s.accp[half][i0][j0 + 4] =
            make_float4(acc[4], acc[5], acc[6], acc[7]);
    }
    __syncthreads();

    // ---- F2: wt = sigmoid(acc0+acc1); out = gx(fp32 from L2) * wt ----
    {
        int i = (tid >> 4) & 31;
        int j4 = (tid & 15) << 2;
        float4 p0 = *(const float4*)&s.accp[0][i][j4];
        float4 p1 = *(const float4*)&s.accp[1][i][j4];
        float4 wv = make_float4(sigf(p0.x + p1.x), sigf(p0.y + p1.y),
                                sigf(p0.z + p1.z), sigf(p0.w + p1.w));
        #pragma unroll
        for (int c = 0; c < 8; c++) {
            float4 v = src4[c * 1024 + (rbase + i) * 16 + (j4 >> 2)];
            float4 o4 = make_float4(v.x * wv.x, v.y * wv.y, v.z * wv.z, v.w * wv.w);
            *reinterpret_cast<float4*>(&dst[c * 4096 + (rbase + i) * 64 + j4]) = o4;
        }
    }
}

extern "C" void kernel_launch(void* const* d_in, const int* in_sizes, int n_in,
                              void* d_out, int out_size) {
    (void)in_sizes; (void)n_in; (void)out_size;
    const float* x   = (const float*)d_in[0];
    const float* w1  = (const float*)d_in[1];
    const float* b1  = (const float*)d_in[2];
    const float* w3  = (const float*)d_in[3];
    const float* b3  = (const float*)d_in[4];
    const float* gnw = (const float*)d_in[5];
    const float* gnb = (const float*)d_in[6];
    float* out = (float*)d_out;

    size_t smem = sizeof(SmC);
    cudaFuncSetAttribute(fused_kernel, cudaFuncAttributeMaxDynamicSharedMemorySize, (int)smem);
    fused_kernel<<<2048, NTH, smem>>>(x, w1, b1, w3, b3, gnw, gnb, out);
}